// round 1
// baseline (speedup 1.0000x reference)
#include <cuda_runtime.h>
#include <math.h>
#include <stdint.h>

#define SEQ   4096
#define INDIM 64
#define D     1024
#define G     4096      // 4*D
#define NCTA  148
#define RTHR  512

// ---------------- scratch (device globals: allocation-free) ----------------
__device__ float g_x [(size_t)SEQ * D];        // 16 MB  leaky(inp@W1^T+b1)
__device__ float g_xg[(size_t)SEQ * G];        // 64 MB  per-step gate preactivations
__device__ float g_h1[(size_t)SEQ * D];        // 16 MB  layer-1 hidden history
__device__ float g_hbuf[2][D];                 // h double buffer
__device__ unsigned g_bar_count;
__device__ unsigned g_bar_flag;

// ---------------- init: zero h0 + barrier state ----------------
__global__ void init_state_kernel() {
    int tid = threadIdx.x;
    if (tid < D) { g_hbuf[0][tid] = 0.f; g_hbuf[1][tid] = 0.f; }
    if (tid == 0) { g_bar_count = 0u; g_bar_flag = 0u; }
}

// ---------------- SGEMM: C[M,N] = A[M,K] @ B[N,K]^T + bias1 (+bias2), opt leaky ----------------
// BM=BN=128, BK=8, 256 threads, 8x8 per thread.
template<bool RELU>
__global__ __launch_bounds__(256) void sgemm_nt(
    const float* __restrict__ A, const float* __restrict__ B,
    float* __restrict__ C,
    const float* __restrict__ bias1, const float* __restrict__ bias2,
    int M, int N, int K)
{
    __shared__ __align__(16) float As[8][132];
    __shared__ __align__(16) float Bs[8][132];

    const int tid = threadIdx.x;
    const int bm = blockIdx.y, bn = blockIdx.x;
    const int ty = tid >> 4, tx = tid & 15;        // 16x16 thread grid
    const int lrow = tid >> 1;                     // 0..127
    const int lcol = (tid & 1) * 4;                // 0 or 4

    const float* Aptr = A + (size_t)(bm * 128 + lrow) * K + lcol;
    const float* Bptr = B + (size_t)(bn * 128 + lrow) * K + lcol;

    float acc[8][8];
    #pragma unroll
    for (int i = 0; i < 8; i++)
        #pragma unroll
        for (int j = 0; j < 8; j++) acc[i][j] = 0.f;

    for (int k0 = 0; k0 < K; k0 += 8) {
        float4 a = *(const float4*)(Aptr + k0);
        float4 b = *(const float4*)(Bptr + k0);
        __syncthreads();
        As[lcol + 0][lrow] = a.x; As[lcol + 1][lrow] = a.y;
        As[lcol + 2][lrow] = a.z; As[lcol + 3][lrow] = a.w;
        Bs[lcol + 0][lrow] = b.x; Bs[lcol + 1][lrow] = b.y;
        Bs[lcol + 2][lrow] = b.z; Bs[lcol + 3][lrow] = b.w;
        __syncthreads();
        #pragma unroll
        for (int k = 0; k < 8; k++) {
            float4 a0 = *(const float4*)&As[k][ty * 8];
            float4 a1 = *(const float4*)&As[k][ty * 8 + 4];
            float4 b0 = *(const float4*)&Bs[k][tx * 8];
            float4 b1 = *(const float4*)&Bs[k][tx * 8 + 4];
            float av[8] = {a0.x,a0.y,a0.z,a0.w,a1.x,a1.y,a1.z,a1.w};
            float bv[8] = {b0.x,b0.y,b0.z,b0.w,b1.x,b1.y,b1.z,b1.w};
            #pragma unroll
            for (int i = 0; i < 8; i++)
                #pragma unroll
                for (int j = 0; j < 8; j++)
                    acc[i][j] = fmaf(av[i], bv[j], acc[i][j]);
        }
    }

    const int colbase = bn * 128 + tx * 8;
    float bb[8];
    #pragma unroll
    for (int j = 0; j < 8; j++) {
        float v = bias1 ? bias1[colbase + j] : 0.f;
        if (bias2) v += bias2[colbase + j];
        bb[j] = v;
    }
    #pragma unroll
    for (int i = 0; i < 8; i++) {
        int row = bm * 128 + ty * 8 + i;
        float* Crow = C + (size_t)row * N + colbase;
        float o[8];
        #pragma unroll
        for (int j = 0; j < 8; j++) {
            float v = acc[i][j] + bb[j];
            if (RELU) v = v > 0.f ? v : 0.01f * v;
            o[j] = v;
        }
        *(float4*)(Crow)     = make_float4(o[0], o[1], o[2], o[3]);
        *(float4*)(Crow + 4) = make_float4(o[4], o[5], o[6], o[7]);
    }
}

// ---------------- persistent LSTM recurrence ----------------
// 148 CTAs x 512 thr. CTA owns 6-7 units (24-28 gate rows). Whh rows live in
// registers: warp w holds rows 2w,2w+1 as float4[8] per thread (thread = float4
// column j*32+lane). h_prev staged in smem each step; one grid barrier / step.
__device__ __forceinline__ float sigmoidf_(float x) { return 1.f / (1.f + expf(-x)); }

__global__ __launch_bounds__(RTHR, 1) void lstm_recur_kernel(
    const float* __restrict__ Whh,   // [G][D] this layer
    const float* __restrict__ xg,    // [SEQ][G]
    float* __restrict__ h_hist,      // layer-0: g_h1, else unused
    float* __restrict__ out,         // layer-1: final output, else unused
    int store_hist, int store_out)
{
    __shared__ __align__(16) float4 hs4[D / 4];   // h_prev, 1024 floats
    __shared__ float gs[32];
    __shared__ float xgs[32];
    __shared__ int   growtab[32];
    __shared__ float c_s[8];

    const int tid  = threadIdx.x;
    const int lane = tid & 31;
    const int wid  = tid >> 5;
    const int cta  = blockIdx.x;

    const int u_begin = (cta * D) / NCTA;
    const int u_end   = ((cta + 1) * D) / NCTA;
    const int nu      = u_end - u_begin;       // 6 or 7
    const int nrows   = 4 * nu;                // 24 or 28

    if (tid < nrows) {
        int gate = tid / nu, ui = tid % nu;
        growtab[tid] = gate * D + u_begin + ui;  // global gate-row index
    }
    if (tid < nu) c_s[tid] = 0.f;
    __syncthreads();

    // Load this warp's two weight rows into registers (64 regs/thread).
    const int r0 = wid * 2, r1 = r0 + 1;
    const bool act = (r0 < nrows);
    float4 wv0[8], wv1[8];
    if (act) {
        const float4* Wr0 = (const float4*)(Whh + (size_t)growtab[r0] * D);
        const float4* Wr1 = (const float4*)(Whh + (size_t)growtab[r1] * D);
        #pragma unroll
        for (int j = 0; j < 8; j++) {
            wv0[j] = Wr0[j * 32 + lane];
            wv1[j] = Wr1[j * 32 + lane];
        }
    }

    for (int t = 0; t < SEQ; t++) {
        // stage h_prev (L2, bypass L1: cross-SM producer) and xg row slice
        if (tid < 256) {
            hs4[tid] = __ldcg(((const float4*)g_hbuf[t & 1]) + tid);
        } else if (tid - 256 < nrows) {
            int r = tid - 256;
            xgs[r] = __ldg(&xg[(size_t)t * G + growtab[r]]);
        }
        __syncthreads();

        if (act) {
            float acc0 = 0.f, acc1 = 0.f;
            #pragma unroll
            for (int j = 0; j < 8; j++) {
                float4 h4 = hs4[j * 32 + lane];
                acc0 = fmaf(wv0[j].x, h4.x, acc0); acc0 = fmaf(wv0[j].y, h4.y, acc0);
                acc0 = fmaf(wv0[j].z, h4.z, acc0); acc0 = fmaf(wv0[j].w, h4.w, acc0);
                acc1 = fmaf(wv1[j].x, h4.x, acc1); acc1 = fmaf(wv1[j].y, h4.y, acc1);
                acc1 = fmaf(wv1[j].z, h4.z, acc1); acc1 = fmaf(wv1[j].w, h4.w, acc1);
            }
            #pragma unroll
            for (int off = 16; off; off >>= 1) {
                acc0 += __shfl_xor_sync(0xffffffffu, acc0, off);
                acc1 += __shfl_xor_sync(0xffffffffu, acc1, off);
            }
            if (lane == 0) { gs[r0] = acc0; gs[r1] = acc1; }
        }
        __syncthreads();

        if (tid < nu) {
            float gi = gs[0 * nu + tid] + xgs[0 * nu + tid];
            float gf = gs[1 * nu + tid] + xgs[1 * nu + tid];
            float gg = gs[2 * nu + tid] + xgs[2 * nu + tid];
            float go = gs[3 * nu + tid] + xgs[3 * nu + tid];
            float c = c_s[tid];
            c = sigmoidf_(gf) * c + sigmoidf_(gi) * tanhf(gg);
            float h = sigmoidf_(go) * tanhf(c);
            c_s[tid] = c;
            int u = u_begin + tid;
            g_hbuf[(t + 1) & 1][u] = h;
            if (store_hist) h_hist[(size_t)t * D + u] = h;
            if (store_out && t == SEQ - 1) out[u] = h > 0.f ? h : 0.01f * h;
            __threadfence();   // make h visible GPU-wide before the barrier arrive
        }
        __syncthreads();

        // grid barrier (one per step): counting arrive + broadcast flag
        if (tid == 0) {
            unsigned want = (unsigned)(t + 1);
            unsigned arr = atomicAdd(&g_bar_count, 1u) + 1u;
            if (arr == want * NCTA) {
                __threadfence();
                *(volatile unsigned*)&g_bar_flag = want;   // release (fence above)
            } else {
                while (*(volatile unsigned*)&g_bar_flag < want) { }
                __threadfence();                           // acquire
            }
        }
        __syncthreads();
    }
}

// ---------------- launch ----------------
extern "C" void kernel_launch(void* const* d_in, const int* in_sizes, int n_in,
                              void* d_out, int out_size)
{
    const float* inp = (const float*)d_in[0];   // (4096, 64)
    const float* W1  = (const float*)d_in[1];   // (1024, 64)
    const float* b1  = (const float*)d_in[2];   // (1024,)
    const float* Wih = (const float*)d_in[3];   // (2, 4096, 1024)
    const float* Whh = (const float*)d_in[4];   // (2, 4096, 1024)
    const float* bih = (const float*)d_in[5];   // (2, 4096)
    const float* bhh = (const float*)d_in[6];   // (2, 4096)
    float* out = (float*)d_out;                 // (1,1,1024)

    float *gx, *gxg, *gh1;
    cudaGetSymbolAddress((void**)&gx,  g_x);
    cudaGetSymbolAddress((void**)&gxg, g_xg);
    cudaGetSymbolAddress((void**)&gh1, g_h1);

    // Phase A: x = leaky_relu(inp @ W1^T + b1)       [4096 x 1024, K=64]
    sgemm_nt<true><<<dim3(D / 128, SEQ / 128), 256>>>(
        inp, W1, gx, b1, nullptr, SEQ, D, INDIM);

    // Phase B: xg1 = x @ Wih1^T + (bih1 + bhh1)      [4096 x 4096, K=1024]
    sgemm_nt<false><<<dim3(G / 128, SEQ / 128), 256>>>(
        gx, Wih, gxg, bih, bhh, SEQ, G, D);

    // Layer-1 recurrence (writes g_h1)
    init_state_kernel<<<1, 1024>>>();
    lstm_recur_kernel<<<NCTA, RTHR>>>(Whh, gxg, gh1, out, 1, 0);

    // Phase C: xg2 = h1 @ Wih2^T + (bih2 + bhh2)
    sgemm_nt<false><<<dim3(G / 128, SEQ / 128), 256>>>(
        gh1, Wih + (size_t)G * D, gxg, bih + G, bhh + G, SEQ, G, D);

    // Layer-2 recurrence (writes final leaky_relu(h_T) to out)
    init_state_kernel<<<1, 1024>>>();
    lstm_recur_kernel<<<NCTA, RTHR>>>(Whh + (size_t)G * D, gxg, gh1, out, 0, 1);
}